// round 5
// baseline (speedup 1.0000x reference)
#include <cuda_runtime.h>

// Problem constants (fixed by reference)
#define BSZ   256      // batch
#define HID   1024     // hidden
#define OUTD  768      // output / input feature dim

// Tiling
#define BM 64          // batch rows per block
#define BN 32          // hidden units (or out features) per block
#define KT 16          // k-tile
#define XLD 72         // xs row stride (BM + 8, conflict-free transpose stores, 8B-aligned pair reads)
#define WLD 33         // ws row stride (BN + 1)

typedef unsigned long long u64;

// h ping-pong buffers (allocation-free scratch)
__device__ float g_h[2][BSZ * HID];

static __device__ __forceinline__ u64 pk2(float v) {
    u64 r; asm("mov.b64 %0, {%1, %1};" : "=l"(r) : "f"(v)); return r;
}
static __device__ __forceinline__ void fma2(u64& a, u64 x, u64 w) {
    asm("fma.rn.f32x2 %0, %1, %2, %0;" : "+l"(a) : "l"(x), "l"(w));
}
static __device__ __forceinline__ float f2lo(u64 a) { return __uint_as_float((unsigned)a); }
static __device__ __forceinline__ float f2hi(u64 a) { return __uint_as_float((unsigned)(a >> 32)); }
static __device__ __forceinline__ float sigm(float x) {
    return __fdividef(1.f, 1.f + __expf(-x));
}

// ---------------------------------------------------------------------------
// Fused GRU gate kernel: computes h_new = GRUCell(x, h_prev) for one step.
// Accumulates over two K phases: x @ W_ih^T (K=768) and h @ W_hh^T (K=1024),
// keeping 4 accumulator groups per output element (r, z, i_n, h_n).
// Thread layout: 32 (n) x 8 (row-groups); each thread: 1 hidden unit x 8 batch
// rows as 4 packed f32x2 pairs -> 12 fma.f32x2 per k per thread.
// ---------------------------------------------------------------------------
__global__ __launch_bounds__(256, 1) void gru_gates_kernel(
    const float* __restrict__ x,
    const float* __restrict__ Wih, const float* __restrict__ Whh,
    const float* __restrict__ bih, const float* __restrict__ bhh,
    int p)
{
    __shared__ __align__(16) float xs[KT][XLD];
    __shared__ __align__(16) float ws[3][KT][WLD];

    const float* __restrict__ hprev = g_h[p];
    float* __restrict__ hnew = g_h[p ^ 1];

    const int tx = threadIdx.x;            // 0..31 -> n within tile
    const int ty = threadIdx.y;            // 0..7  -> 8-row group
    const int tid = ty * 32 + tx;
    const int n0 = blockIdx.x * BN;
    const int m0 = blockIdx.y * BM;

    // staging assignments
    const int xr = tid >> 2;               // 0..63 batch row
    const int xk = (tid & 3) << 2;         // 0,4,8,12 k offset (float4)
    const int wn = tid >> 3;               // 0..31 weight row (unit)
    const int wk = (tid & 7) << 1;         // 0,2,..,14 k offset (float2)

    u64 accR[4]  = {0, 0, 0, 0};
    u64 accZ[4]  = {0, 0, 0, 0};
    u64 accIN[4] = {0, 0, 0, 0};
    u64 accHN[4] = {0, 0, 0, 0};

#pragma unroll
    for (int ph = 0; ph < 2; ++ph) {
        const float* src = ph ? hprev : x;
        const float* W   = ph ? Whh : Wih;
        const int ldS    = ph ? HID : OUTD;
        const int ntile  = ldS / KT;

        const float* xp_g = src + (size_t)(m0 + xr) * ldS + xk;
        const float* w0_g = W + (size_t)(n0 + wn) * ldS + wk;
        const float* w1_g = w0_g + (size_t)HID * ldS;
        const float* w2_g = w1_g + (size_t)HID * ldS;

        // prefetch tile 0
        float4 xf  = *(const float4*)xp_g;
        float2 wf0 = *(const float2*)w0_g;
        float2 wf1 = *(const float2*)w1_g;
        float2 wf2 = *(const float2*)w2_g;

        for (int kt = 0; kt < ntile; ++kt) {
            __syncthreads();   // previous tile's compute done
            xs[xk + 0][xr] = xf.x; xs[xk + 1][xr] = xf.y;
            xs[xk + 2][xr] = xf.z; xs[xk + 3][xr] = xf.w;
            ws[0][wk][wn] = wf0.x; ws[0][wk + 1][wn] = wf0.y;
            ws[1][wk][wn] = wf1.x; ws[1][wk + 1][wn] = wf1.y;
            ws[2][wk][wn] = wf2.x; ws[2][wk + 1][wn] = wf2.y;
            __syncthreads();

            // software pipeline: fetch next tile while computing this one
            if (kt + 1 < ntile) {
                const int off = (kt + 1) * KT;
                xf  = *(const float4*)(xp_g + off);
                wf0 = *(const float2*)(w0_g + off);
                wf1 = *(const float2*)(w1_g + off);
                wf2 = *(const float2*)(w2_g + off);
            }

#pragma unroll
            for (int k = 0; k < KT; ++k) {
                const u64 wr2 = pk2(ws[0][k][tx]);
                const u64 wz2 = pk2(ws[1][k][tx]);
                const u64 wn2 = pk2(ws[2][k][tx]);
                const u64* xv = (const u64*)&xs[k][ty * 8];
#pragma unroll
                for (int i = 0; i < 4; ++i) {
                    const u64 xi = xv[i];
                    fma2(accR[i], xi, wr2);
                    fma2(accZ[i], xi, wz2);
                    if (ph == 0) fma2(accIN[i], xi, wn2);
                    else         fma2(accHN[i], xi, wn2);
                }
            }
        }
    }

    // epilogue: gate nonlinearities + blend
    const int n = n0 + tx;
    const float br   = bih[n] + bhh[n];
    const float bz   = bih[HID + n] + bhh[HID + n];
    const float bin_ = bih[2 * HID + n];
    const float bhn  = bhh[2 * HID + n];

#pragma unroll
    for (int i = 0; i < 4; ++i) {
#pragma unroll
        for (int j = 0; j < 2; ++j) {
            const int m = m0 + ty * 8 + i * 2 + j;
            const float aR = j ? f2hi(accR[i])  : f2lo(accR[i]);
            const float aZ = j ? f2hi(accZ[i])  : f2lo(accZ[i]);
            const float aI = j ? f2hi(accIN[i]) : f2lo(accIN[i]);
            const float aH = j ? f2hi(accHN[i]) : f2lo(accHN[i]);
            const float r  = sigm(aR + br);
            const float z  = sigm(aZ + bz);
            const float nn = tanhf(aI + bin_ + r * (aH + bhn));
            const float hp = hprev[(size_t)m * HID + n];
            hnew[(size_t)m * HID + n] = (1.f - z) * nn + z * hp;
        }
    }
}

// ---------------------------------------------------------------------------
// FC kernel: y = h_new @ W_fc^T + b_fc, written straight into out[t]
// (out[t] is also next step's x -> no extra buffer).
// ---------------------------------------------------------------------------
__global__ __launch_bounds__(256, 1) void fc_kernel(
    const float* __restrict__ Wfc, const float* __restrict__ bfc,
    float* __restrict__ y, int p)
{
    __shared__ __align__(16) float xs[KT][XLD];
    __shared__ __align__(16) float ws[KT][WLD];

    const float* __restrict__ h = g_h[p ^ 1];   // h_new written by gates kernel

    const int tx = threadIdx.x;
    const int ty = threadIdx.y;
    const int tid = ty * 32 + tx;
    const int n0 = blockIdx.x * BN;
    const int m0 = blockIdx.y * BM;

    const int xr = tid >> 2;
    const int xk = (tid & 3) << 2;
    const int wn = tid >> 3;
    const int wk = (tid & 7) << 1;

    u64 acc[4] = {0, 0, 0, 0};

    const float* xp_g = h + (size_t)(m0 + xr) * HID + xk;
    const float* w_g  = Wfc + (size_t)(n0 + wn) * HID + wk;

    float4 xf = *(const float4*)xp_g;
    float2 wf = *(const float2*)w_g;

    const int ntile = HID / KT;
    for (int kt = 0; kt < ntile; ++kt) {
        __syncthreads();
        xs[xk + 0][xr] = xf.x; xs[xk + 1][xr] = xf.y;
        xs[xk + 2][xr] = xf.z; xs[xk + 3][xr] = xf.w;
        ws[wk][wn] = wf.x; ws[wk + 1][wn] = wf.y;
        __syncthreads();

        if (kt + 1 < ntile) {
            const int off = (kt + 1) * KT;
            xf = *(const float4*)(xp_g + off);
            wf = *(const float2*)(w_g + off);
        }

#pragma unroll
        for (int k = 0; k < KT; ++k) {
            const u64 w2 = pk2(ws[k][tx]);
            const u64* xv = (const u64*)&xs[k][ty * 8];
#pragma unroll
            for (int i = 0; i < 4; ++i)
                fma2(acc[i], xv[i], w2);
        }
    }

    const int n = n0 + tx;
    const float bv = bfc[n];
#pragma unroll
    for (int i = 0; i < 4; ++i) {
#pragma unroll
        for (int j = 0; j < 2; ++j) {
            const int m = m0 + ty * 8 + i * 2 + j;
            const float v = (j ? f2hi(acc[i]) : f2lo(acc[i])) + bv;
            y[(size_t)m * OUTD + n] = v;
        }
    }
}

__global__ void init_h_kernel(const float* __restrict__ hidden) {
    const int i = blockIdx.x * blockDim.x + threadIdx.x;
    if (i < BSZ * HID) g_h[0][i] = hidden[i];
}

extern "C" void kernel_launch(void* const* d_in, const int* in_sizes, int n_in,
                              void* d_out, int out_size) {
    const float* src    = (const float*)d_in[0];
    // d_in[1]: tgt (int64) — only its shape (T) matters
    const float* hidden = (const float*)d_in[2];
    const float* Wih    = (const float*)d_in[3];
    const float* Whh    = (const float*)d_in[4];
    const float* bih    = (const float*)d_in[5];
    const float* bhh    = (const float*)d_in[6];
    const float* Wfc    = (const float*)d_in[7];
    const float* bfc    = (const float*)d_in[8];
    float* out          = (float*)d_out;

    const int T = in_sizes[1] / BSZ;   // tgt has T*B elements

    init_h_kernel<<<(BSZ * HID + 511) / 512, 512>>>(hidden);

    const dim3 blk(32, 8);
    const dim3 g_gates(HID / BN, BSZ / BM);   // 32 x 4 = 128 blocks
    const dim3 g_fc(OUTD / BN, BSZ / BM);     // 24 x 4 = 96 blocks

    for (int t = 0; t < T; ++t) {
        const float* x = (t == 0) ? src : out + (size_t)(t - 1) * BSZ * OUTD;
        const int p = t & 1;
        gru_gates_kernel<<<g_gates, blk>>>(x, Wih, Whh, bih, bhh, p);
        fc_kernel<<<g_fc, blk>>>(Wfc, bfc, out + (size_t)t * BSZ * OUTD, p);
    }
}

// round 6
// speedup vs baseline: 1.0008x; 1.0008x over previous
#include <cuda_runtime.h>

// Problem constants (fixed by reference)
#define BSZ   256      // batch
#define HID   1024     // hidden
#define OUTD  768      // output / input feature dim

// Tiling
#define BM 64          // batch rows per block
#define BN 32          // hidden units (or out features) per block
#define KT 16          // k-tile
#define XLD 72         // xs row stride (BM + 8, conflict-free transpose stores, 8B-aligned pair reads)
#define WLD 33         // ws row stride (BN + 1)

typedef unsigned long long u64;

// h ping-pong buffers (allocation-free scratch)
__device__ float g_h[2][BSZ * HID];

static __device__ __forceinline__ u64 pk2(float v) {
    u64 r; asm("mov.b64 %0, {%1, %1};" : "=l"(r) : "f"(v)); return r;
}
static __device__ __forceinline__ void fma2(u64& a, u64 x, u64 w) {
    asm("fma.rn.f32x2 %0, %1, %2, %0;" : "+l"(a) : "l"(x), "l"(w));
}
static __device__ __forceinline__ float f2lo(u64 a) { return __uint_as_float((unsigned)a); }
static __device__ __forceinline__ float f2hi(u64 a) { return __uint_as_float((unsigned)(a >> 32)); }
static __device__ __forceinline__ float sigm(float x) {
    return __fdividef(1.f, 1.f + __expf(-x));
}

// ---------------------------------------------------------------------------
// Fused GRU gate kernel: computes h_new = GRUCell(x, h_prev) for one step.
// Accumulates over two K phases: x @ W_ih^T (K=768) and h @ W_hh^T (K=1024),
// keeping 4 accumulator groups per output element (r, z, i_n, h_n).
// Thread layout: 32 (n) x 8 (row-groups); each thread: 1 hidden unit x 8 batch
// rows as 4 packed f32x2 pairs -> 12 fma.f32x2 per k per thread.
// ---------------------------------------------------------------------------
__global__ __launch_bounds__(256, 1) void gru_gates_kernel(
    const float* __restrict__ x,
    const float* __restrict__ Wih, const float* __restrict__ Whh,
    const float* __restrict__ bih, const float* __restrict__ bhh,
    int p)
{
    __shared__ __align__(16) float xs[KT][XLD];
    __shared__ __align__(16) float ws[3][KT][WLD];

    const float* __restrict__ hprev = g_h[p];
    float* __restrict__ hnew = g_h[p ^ 1];

    const int tx = threadIdx.x;            // 0..31 -> n within tile
    const int ty = threadIdx.y;            // 0..7  -> 8-row group
    const int tid = ty * 32 + tx;
    const int n0 = blockIdx.x * BN;
    const int m0 = blockIdx.y * BM;

    // staging assignments
    const int xr = tid >> 2;               // 0..63 batch row
    const int xk = (tid & 3) << 2;         // 0,4,8,12 k offset (float4)
    const int wn = tid >> 3;               // 0..31 weight row (unit)
    const int wk = (tid & 7) << 1;         // 0,2,..,14 k offset (float2)

    u64 accR[4]  = {0, 0, 0, 0};
    u64 accZ[4]  = {0, 0, 0, 0};
    u64 accIN[4] = {0, 0, 0, 0};
    u64 accHN[4] = {0, 0, 0, 0};

#pragma unroll
    for (int ph = 0; ph < 2; ++ph) {
        const float* src = ph ? hprev : x;
        const float* W   = ph ? Whh : Wih;
        const int ldS    = ph ? HID : OUTD;
        const int ntile  = ldS / KT;

        const float* xp_g = src + (size_t)(m0 + xr) * ldS + xk;
        const float* w0_g = W + (size_t)(n0 + wn) * ldS + wk;
        const float* w1_g = w0_g + (size_t)HID * ldS;
        const float* w2_g = w1_g + (size_t)HID * ldS;

        // prefetch tile 0
        float4 xf  = *(const float4*)xp_g;
        float2 wf0 = *(const float2*)w0_g;
        float2 wf1 = *(const float2*)w1_g;
        float2 wf2 = *(const float2*)w2_g;

        for (int kt = 0; kt < ntile; ++kt) {
            __syncthreads();   // previous tile's compute done
            xs[xk + 0][xr] = xf.x; xs[xk + 1][xr] = xf.y;
            xs[xk + 2][xr] = xf.z; xs[xk + 3][xr] = xf.w;
            ws[0][wk][wn] = wf0.x; ws[0][wk + 1][wn] = wf0.y;
            ws[1][wk][wn] = wf1.x; ws[1][wk + 1][wn] = wf1.y;
            ws[2][wk][wn] = wf2.x; ws[2][wk + 1][wn] = wf2.y;
            __syncthreads();

            // software pipeline: fetch next tile while computing this one
            if (kt + 1 < ntile) {
                const int off = (kt + 1) * KT;
                xf  = *(const float4*)(xp_g + off);
                wf0 = *(const float2*)(w0_g + off);
                wf1 = *(const float2*)(w1_g + off);
                wf2 = *(const float2*)(w2_g + off);
            }

#pragma unroll
            for (int k = 0; k < KT; ++k) {
                const u64 wr2 = pk2(ws[0][k][tx]);
                const u64 wz2 = pk2(ws[1][k][tx]);
                const u64 wn2 = pk2(ws[2][k][tx]);
                const u64* xv = (const u64*)&xs[k][ty * 8];
#pragma unroll
                for (int i = 0; i < 4; ++i) {
                    const u64 xi = xv[i];
                    fma2(accR[i], xi, wr2);
                    fma2(accZ[i], xi, wz2);
                    if (ph == 0) fma2(accIN[i], xi, wn2);
                    else         fma2(accHN[i], xi, wn2);
                }
            }
        }
    }

    // epilogue: gate nonlinearities + blend
    const int n = n0 + tx;
    const float br   = bih[n] + bhh[n];
    const float bz   = bih[HID + n] + bhh[HID + n];
    const float bin_ = bih[2 * HID + n];
    const float bhn  = bhh[2 * HID + n];

#pragma unroll
    for (int i = 0; i < 4; ++i) {
#pragma unroll
        for (int j = 0; j < 2; ++j) {
            const int m = m0 + ty * 8 + i * 2 + j;
            const float aR = j ? f2hi(accR[i])  : f2lo(accR[i]);
            const float aZ = j ? f2hi(accZ[i])  : f2lo(accZ[i]);
            const float aI = j ? f2hi(accIN[i]) : f2lo(accIN[i]);
            const float aH = j ? f2hi(accHN[i]) : f2lo(accHN[i]);
            const float r  = sigm(aR + br);
            const float z  = sigm(aZ + bz);
            const float nn = tanhf(aI + bin_ + r * (aH + bhn));
            const float hp = hprev[(size_t)m * HID + n];
            hnew[(size_t)m * HID + n] = (1.f - z) * nn + z * hp;
        }
    }
}

// ---------------------------------------------------------------------------
// FC kernel: y = h_new @ W_fc^T + b_fc, written straight into out[t]
// (out[t] is also next step's x -> no extra buffer).
// ---------------------------------------------------------------------------
__global__ __launch_bounds__(256, 1) void fc_kernel(
    const float* __restrict__ Wfc, const float* __restrict__ bfc,
    float* __restrict__ y, int p)
{
    __shared__ __align__(16) float xs[KT][XLD];
    __shared__ __align__(16) float ws[KT][WLD];

    const float* __restrict__ h = g_h[p ^ 1];   // h_new written by gates kernel

    const int tx = threadIdx.x;
    const int ty = threadIdx.y;
    const int tid = ty * 32 + tx;
    const int n0 = blockIdx.x * BN;
    const int m0 = blockIdx.y * BM;

    const int xr = tid >> 2;
    const int xk = (tid & 3) << 2;
    const int wn = tid >> 3;
    const int wk = (tid & 7) << 1;

    u64 acc[4] = {0, 0, 0, 0};

    const float* xp_g = h + (size_t)(m0 + xr) * HID + xk;
    const float* w_g  = Wfc + (size_t)(n0 + wn) * HID + wk;

    float4 xf = *(const float4*)xp_g;
    float2 wf = *(const float2*)w_g;

    const int ntile = HID / KT;
    for (int kt = 0; kt < ntile; ++kt) {
        __syncthreads();
        xs[xk + 0][xr] = xf.x; xs[xk + 1][xr] = xf.y;
        xs[xk + 2][xr] = xf.z; xs[xk + 3][xr] = xf.w;
        ws[wk][wn] = wf.x; ws[wk + 1][wn] = wf.y;
        __syncthreads();

        if (kt + 1 < ntile) {
            const int off = (kt + 1) * KT;
            xf = *(const float4*)(xp_g + off);
            wf = *(const float2*)(w_g + off);
        }

#pragma unroll
        for (int k = 0; k < KT; ++k) {
            const u64 w2 = pk2(ws[k][tx]);
            const u64* xv = (const u64*)&xs[k][ty * 8];
#pragma unroll
            for (int i = 0; i < 4; ++i)
                fma2(acc[i], xv[i], w2);
        }
    }

    const int n = n0 + tx;
    const float bv = bfc[n];
#pragma unroll
    for (int i = 0; i < 4; ++i) {
#pragma unroll
        for (int j = 0; j < 2; ++j) {
            const int m = m0 + ty * 8 + i * 2 + j;
            const float v = (j ? f2hi(acc[i]) : f2lo(acc[i])) + bv;
            y[(size_t)m * OUTD + n] = v;
        }
    }
}

__global__ void init_h_kernel(const float* __restrict__ hidden) {
    const int i = blockIdx.x * blockDim.x + threadIdx.x;
    if (i < BSZ * HID) g_h[0][i] = hidden[i];
}

extern "C" void kernel_launch(void* const* d_in, const int* in_sizes, int n_in,
                              void* d_out, int out_size) {
    const float* src    = (const float*)d_in[0];
    // d_in[1]: tgt (int64) — only its shape (T) matters
    const float* hidden = (const float*)d_in[2];
    const float* Wih    = (const float*)d_in[3];
    const float* Whh    = (const float*)d_in[4];
    const float* bih    = (const float*)d_in[5];
    const float* bhh    = (const float*)d_in[6];
    const float* Wfc    = (const float*)d_in[7];
    const float* bfc    = (const float*)d_in[8];
    float* out          = (float*)d_out;

    const int T = in_sizes[1] / BSZ;   // tgt has T*B elements

    init_h_kernel<<<(BSZ * HID + 511) / 512, 512>>>(hidden);

    const dim3 blk(32, 8);
    const dim3 g_gates(HID / BN, BSZ / BM);   // 32 x 4 = 128 blocks
    const dim3 g_fc(OUTD / BN, BSZ / BM);     // 24 x 4 = 96 blocks

    for (int t = 0; t < T; ++t) {
        const float* x = (t == 0) ? src : out + (size_t)(t - 1) * BSZ * OUTD;
        const int p = t & 1;
        gru_gates_kernel<<<g_gates, blk>>>(x, Wih, Whh, bih, bhh, p);
        fc_kernel<<<g_fc, blk>>>(Wfc, bfc, out + (size_t)t * BSZ * OUTD, p);
    }
}

// round 7
// speedup vs baseline: 1.0189x; 1.0181x over previous
#include <cuda_runtime.h>

// Problem constants (fixed by reference)
#define BSZ   256      // batch
#define HID   1024     // hidden
#define OUTD  768      // output / input feature dim

// Tiling
#define BM 64          // batch rows per block
#define BN 32          // hidden units (or out features) per block
#define KT 16          // k-tile
#define XLD 72         // xs row stride (BM + 8, conflict-free transpose stores, 8B-aligned pair reads)
#define WLD 33         // ws row stride (BN + 1)

typedef unsigned long long u64;

// h ping-pong buffers (allocation-free scratch)
__device__ float g_h[2][BSZ * HID];

static __device__ __forceinline__ u64 pk2(float v) {
    u64 r; asm("mov.b64 %0, {%1, %1};" : "=l"(r) : "f"(v)); return r;
}
static __device__ __forceinline__ void fma2(u64& a, u64 x, u64 w) {
    asm("fma.rn.f32x2 %0, %1, %2, %0;" : "+l"(a) : "l"(x), "l"(w));
}
static __device__ __forceinline__ float f2lo(u64 a) { return __uint_as_float((unsigned)a); }
static __device__ __forceinline__ float f2hi(u64 a) { return __uint_as_float((unsigned)(a >> 32)); }
static __device__ __forceinline__ float sigm(float x) {
    return __fdividef(1.f, 1.f + __expf(-x));
}

// ---------------------------------------------------------------------------
// Fused GRU gate kernel: computes h_new = GRUCell(x, h_prev) for one step.
// Accumulates over two K phases: x @ W_ih^T (K=768) and h @ W_hh^T (K=1024),
// keeping 4 accumulator groups per output element (r, z, i_n, h_n).
// Thread layout: 32 (n) x 8 (row-groups); each thread: 1 hidden unit x 8 batch
// rows as 4 packed f32x2 pairs -> 12 fma.f32x2 per k per thread.
// ---------------------------------------------------------------------------
__global__ __launch_bounds__(256, 1) void gru_gates_kernel(
    const float* __restrict__ x,
    const float* __restrict__ Wih, const float* __restrict__ Whh,
    const float* __restrict__ bih, const float* __restrict__ bhh,
    int p)
{
    __shared__ __align__(16) float xs[KT][XLD];
    __shared__ __align__(16) float ws[3][KT][WLD];

    const float* __restrict__ hprev = g_h[p];
    float* __restrict__ hnew = g_h[p ^ 1];

    const int tx = threadIdx.x;            // 0..31 -> n within tile
    const int ty = threadIdx.y;            // 0..7  -> 8-row group
    const int tid = ty * 32 + tx;
    const int n0 = blockIdx.x * BN;
    const int m0 = blockIdx.y * BM;

    // staging assignments
    const int xr = tid >> 2;               // 0..63 batch row
    const int xk = (tid & 3) << 2;         // 0,4,8,12 k offset (float4)
    const int wn = tid >> 3;               // 0..31 weight row (unit)
    const int wk = (tid & 7) << 1;         // 0,2,..,14 k offset (float2)

    u64 accR[4]  = {0, 0, 0, 0};
    u64 accZ[4]  = {0, 0, 0, 0};
    u64 accIN[4] = {0, 0, 0, 0};
    u64 accHN[4] = {0, 0, 0, 0};

#pragma unroll
    for (int ph = 0; ph < 2; ++ph) {
        const float* src = ph ? hprev : x;
        const float* W   = ph ? Whh : Wih;
        const int ldS    = ph ? HID : OUTD;
        const int ntile  = ldS / KT;

        const float* xp_g = src + (size_t)(m0 + xr) * ldS + xk;
        const float* w0_g = W + (size_t)(n0 + wn) * ldS + wk;
        const float* w1_g = w0_g + (size_t)HID * ldS;
        const float* w2_g = w1_g + (size_t)HID * ldS;

        // prefetch tile 0
        float4 xf  = *(const float4*)xp_g;
        float2 wf0 = *(const float2*)w0_g;
        float2 wf1 = *(const float2*)w1_g;
        float2 wf2 = *(const float2*)w2_g;

        for (int kt = 0; kt < ntile; ++kt) {
            __syncthreads();   // previous tile's compute done
            xs[xk + 0][xr] = xf.x; xs[xk + 1][xr] = xf.y;
            xs[xk + 2][xr] = xf.z; xs[xk + 3][xr] = xf.w;
            ws[0][wk][wn] = wf0.x; ws[0][wk + 1][wn] = wf0.y;
            ws[1][wk][wn] = wf1.x; ws[1][wk + 1][wn] = wf1.y;
            ws[2][wk][wn] = wf2.x; ws[2][wk + 1][wn] = wf2.y;
            __syncthreads();

            // software pipeline: fetch next tile while computing this one
            if (kt + 1 < ntile) {
                const int off = (kt + 1) * KT;
                xf  = *(const float4*)(xp_g + off);
                wf0 = *(const float2*)(w0_g + off);
                wf1 = *(const float2*)(w1_g + off);
                wf2 = *(const float2*)(w2_g + off);
            }

#pragma unroll
            for (int k = 0; k < KT; ++k) {
                const u64 wr2 = pk2(ws[0][k][tx]);
                const u64 wz2 = pk2(ws[1][k][tx]);
                const u64 wn2 = pk2(ws[2][k][tx]);
                const u64* xv = (const u64*)&xs[k][ty * 8];
#pragma unroll
                for (int i = 0; i < 4; ++i) {
                    const u64 xi = xv[i];
                    fma2(accR[i], xi, wr2);
                    fma2(accZ[i], xi, wz2);
                    if (ph == 0) fma2(accIN[i], xi, wn2);
                    else         fma2(accHN[i], xi, wn2);
                }
            }
        }
    }

    // epilogue: gate nonlinearities + blend
    const int n = n0 + tx;
    const float br   = bih[n] + bhh[n];
    const float bz   = bih[HID + n] + bhh[HID + n];
    const float bin_ = bih[2 * HID + n];
    const float bhn  = bhh[2 * HID + n];

#pragma unroll
    for (int i = 0; i < 4; ++i) {
#pragma unroll
        for (int j = 0; j < 2; ++j) {
            const int m = m0 + ty * 8 + i * 2 + j;
            const float aR = j ? f2hi(accR[i])  : f2lo(accR[i]);
            const float aZ = j ? f2hi(accZ[i])  : f2lo(accZ[i]);
            const float aI = j ? f2hi(accIN[i]) : f2lo(accIN[i]);
            const float aH = j ? f2hi(accHN[i]) : f2lo(accHN[i]);
            const float r  = sigm(aR + br);
            const float z  = sigm(aZ + bz);
            const float nn = tanhf(aI + bin_ + r * (aH + bhn));
            const float hp = hprev[(size_t)m * HID + n];
            hnew[(size_t)m * HID + n] = (1.f - z) * nn + z * hp;
        }
    }
}

// ---------------------------------------------------------------------------
// FC kernel: y = h_new @ W_fc^T + b_fc, written straight into out[t]
// (out[t] is also next step's x -> no extra buffer).
// ---------------------------------------------------------------------------
__global__ __launch_bounds__(256, 1) void fc_kernel(
    const float* __restrict__ Wfc, const float* __restrict__ bfc,
    float* __restrict__ y, int p)
{
    __shared__ __align__(16) float xs[KT][XLD];
    __shared__ __align__(16) float ws[KT][WLD];

    const float* __restrict__ h = g_h[p ^ 1];   // h_new written by gates kernel

    const int tx = threadIdx.x;
    const int ty = threadIdx.y;
    const int tid = ty * 32 + tx;
    const int n0 = blockIdx.x * BN;
    const int m0 = blockIdx.y * BM;

    const int xr = tid >> 2;
    const int xk = (tid & 3) << 2;
    const int wn = tid >> 3;
    const int wk = (tid & 7) << 1;

    u64 acc[4] = {0, 0, 0, 0};

    const float* xp_g = h + (size_t)(m0 + xr) * HID + xk;
    const float* w_g  = Wfc + (size_t)(n0 + wn) * HID + wk;

    float4 xf = *(const float4*)xp_g;
    float2 wf = *(const float2*)w_g;

    const int ntile = HID / KT;
    for (int kt = 0; kt < ntile; ++kt) {
        __syncthreads();
        xs[xk + 0][xr] = xf.x; xs[xk + 1][xr] = xf.y;
        xs[xk + 2][xr] = xf.z; xs[xk + 3][xr] = xf.w;
        ws[wk][wn] = wf.x; ws[wk + 1][wn] = wf.y;
        __syncthreads();

        if (kt + 1 < ntile) {
            const int off = (kt + 1) * KT;
            xf = *(const float4*)(xp_g + off);
            wf = *(const float2*)(w_g + off);
        }

#pragma unroll
        for (int k = 0; k < KT; ++k) {
            const u64 w2 = pk2(ws[k][tx]);
            const u64* xv = (const u64*)&xs[k][ty * 8];
#pragma unroll
            for (int i = 0; i < 4; ++i)
                fma2(acc[i], xv[i], w2);
        }
    }

    const int n = n0 + tx;
    const float bv = bfc[n];
#pragma unroll
    for (int i = 0; i < 4; ++i) {
#pragma unroll
        for (int j = 0; j < 2; ++j) {
            const int m = m0 + ty * 8 + i * 2 + j;
            const float v = (j ? f2hi(acc[i]) : f2lo(acc[i])) + bv;
            y[(size_t)m * OUTD + n] = v;
        }
    }
}

__global__ void init_h_kernel(const float* __restrict__ hidden) {
    const int i = blockIdx.x * blockDim.x + threadIdx.x;
    if (i < BSZ * HID) g_h[0][i] = hidden[i];
}

extern "C" void kernel_launch(void* const* d_in, const int* in_sizes, int n_in,
                              void* d_out, int out_size) {
    const float* src    = (const float*)d_in[0];
    // d_in[1]: tgt (int64) — only its shape (T) matters
    const float* hidden = (const float*)d_in[2];
    const float* Wih    = (const float*)d_in[3];
    const float* Whh    = (const float*)d_in[4];
    const float* bih    = (const float*)d_in[5];
    const float* bhh    = (const float*)d_in[6];
    const float* Wfc    = (const float*)d_in[7];
    const float* bfc    = (const float*)d_in[8];
    float* out          = (float*)d_out;

    const int T = in_sizes[1] / BSZ;   // tgt has T*B elements

    init_h_kernel<<<(BSZ * HID + 511) / 512, 512>>>(hidden);

    const dim3 blk(32, 8);
    const dim3 g_gates(HID / BN, BSZ / BM);   // 32 x 4 = 128 blocks
    const dim3 g_fc(OUTD / BN, BSZ / BM);     // 24 x 4 = 96 blocks

    for (int t = 0; t < T; ++t) {
        const float* x = (t == 0) ? src : out + (size_t)(t - 1) * BSZ * OUTD;
        const int p = t & 1;
        gru_gates_kernel<<<g_gates, blk>>>(x, Wih, Whh, bih, bhh, p);
        fc_kernel<<<g_fc, blk>>>(Wfc, bfc, out + (size_t)t * BSZ * OUTD, p);
    }
}